// round 17
// baseline (speedup 1.0000x reference)
#include <cuda_runtime.h>
#include <cuda_fp16.h>
#include <cstdint>

#define B_    4
#define S_    2048
#define D_    1024
#define H_    16
#define HD_   64
#define MLP_  4096
#define MROWS (B_*S_)   // 8192
#define QKV_LD 3072     // fused q|k|v row stride
#define HAV_LD 5120     // fused h|av row stride (K of final GEMM)

// ---------------------------------------------------------------------------
// Scratch (device globals) — fp16 activations & weights.
// ---------------------------------------------------------------------------
__device__ __align__(16) uint16_t g_xn  [(size_t)MROWS * D_];
__device__ __align__(16) uint16_t g_qkv [(size_t)MROWS * QKV_LD];
__device__ __align__(16) uint16_t g_hav [(size_t)MROWS * HAV_LD];
__device__ __align__(16) uint16_t g_w1  [(size_t)D_ * MLP_];
__device__ __align__(16) uint16_t g_wqkv[(size_t)D_ * QKV_LD];
__device__ __align__(16) uint16_t g_w2  [(size_t)HAV_LD * D_];   // [w_mlp_out ; w_attn_out]

// ---------------------------------------------------------------------------
// Scalar helpers
// ---------------------------------------------------------------------------
__device__ __forceinline__ uint16_t f2h(float v) {
    return __half_as_ushort(__float2half_rn(v));
}
__device__ __forceinline__ uint32_t pack2h(float a, float b) {
    return (uint32_t)f2h(a) | ((uint32_t)f2h(b) << 16);
}
__device__ __forceinline__ float gelu_tanh(float v) {
    float t = 0.7978845608028654f * (v + 0.044715f * v * v * v);
    return 0.5f * v * (1.0f + tanhf(t));
}

// ---------------------------------------------------------------------------
// PTX helpers
// ---------------------------------------------------------------------------
__device__ __forceinline__ void ldsm4(uint32_t* d, uint32_t a) {
    asm volatile("ldmatrix.sync.aligned.m8n8.x4.shared.b16 {%0,%1,%2,%3}, [%4];"
                 : "=r"(d[0]), "=r"(d[1]), "=r"(d[2]), "=r"(d[3]) : "r"(a));
}
__device__ __forceinline__ void ldsm4t(uint32_t* d, uint32_t a) {
    asm volatile("ldmatrix.sync.aligned.m8n8.x4.trans.shared.b16 {%0,%1,%2,%3}, [%4];"
                 : "=r"(d[0]), "=r"(d[1]), "=r"(d[2]), "=r"(d[3]) : "r"(a));
}
__device__ __forceinline__ void mma16(float* c, const uint32_t* a, const uint32_t* b) {
    asm volatile(
        "mma.sync.aligned.m16n8k16.row.col.f32.f16.f16.f32 "
        "{%0,%1,%2,%3}, {%4,%5,%6,%7}, {%8,%9}, {%0,%1,%2,%3};"
        : "+f"(c[0]), "+f"(c[1]), "+f"(c[2]), "+f"(c[3])
        : "r"(a[0]), "r"(a[1]), "r"(a[2]), "r"(a[3]), "r"(b[0]), "r"(b[1]));
}
__device__ __forceinline__ void cpa16(uint32_t smem, const void* g) {
    asm volatile("cp.async.cg.shared.global [%0], [%1], 16;" :: "r"(smem), "l"(g));
}
#define CP_COMMIT() asm volatile("cp.async.commit_group;")

// ---------------------------------------------------------------------------
// fp32 -> fp16 converts
// ---------------------------------------------------------------------------
__global__ __launch_bounds__(256) void cvt_kernel(
    const float* __restrict__ src, uint16_t* __restrict__ dst, int n)
{
    int i = (blockIdx.x * 256 + threadIdx.x) * 4;
    if (i >= n) return;
    float4 v = *(const float4*)(src + i);
    ushort4 o;
    o.x = f2h(v.x); o.y = f2h(v.y); o.z = f2h(v.z); o.w = f2h(v.w);
    *(ushort4*)(dst + i) = o;
}

// src [D_][D_] -> dst columns [cofs, cofs+D_) of [D_][QKV_LD]
__global__ __launch_bounds__(256) void cvtq_kernel(
    const float* __restrict__ src, uint16_t* __restrict__ dst, int cofs)
{
    int i = (blockIdx.x * 256 + threadIdx.x) * 4;
    int k = i >> 10, n = i & 1023;
    float4 v = *(const float4*)(src + i);
    ushort4 o;
    o.x = f2h(v.x); o.y = f2h(v.y); o.z = f2h(v.z); o.w = f2h(v.w);
    *(ushort4*)(dst + (size_t)k * QKV_LD + cofs + n) = o;
}

// ---------------------------------------------------------------------------
// RMSNorm -> fp16
// ---------------------------------------------------------------------------
__global__ __launch_bounds__(256) void rmsnorm_kernel(
    const float* __restrict__ x, const float* __restrict__ scale,
    uint16_t* __restrict__ o)
{
    int row = blockIdx.x;
    const float4* xr = (const float4*)(x + (size_t)row * D_);
    float4 v = xr[threadIdx.x];
    float s = v.x*v.x + v.y*v.y + v.z*v.z + v.w*v.w;

    __shared__ float red[256];
    red[threadIdx.x] = s;
    __syncthreads();
    #pragma unroll
    for (int off = 128; off > 0; off >>= 1) {
        if (threadIdx.x < off) red[threadIdx.x] += red[threadIdx.x + off];
        __syncthreads();
    }
    float inv = rsqrtf(red[0] * (1.0f / D_) + 1e-6f);

    float4 sc = ((const float4*)scale)[threadIdx.x];
    ushort4 out;
    out.x = f2h(v.x * inv * sc.x);
    out.y = f2h(v.y * inv * sc.y);
    out.z = f2h(v.z * inv * sc.z);
    out.w = f2h(v.w * inv * sc.w);
    *(ushort4*)(o + (size_t)row * D_ + threadIdx.x * 4) = out;
}

// ---------------------------------------------------------------------------
// fp16 GEMM, cp.async 3-stage pipeline. CTA tile 256(M)x128(N), BK=16,
// 256 thr, 8 warps 4(m)x2(n), warp tile 64x64: 8 ldmatrix per 32 HMMA.
// A smem [m][k] stride 24; B smem [k][n] stride 136 — conflict-free.
// DYNAMIC smem (49,920 B > 48 KB static limit — R16 lesson):
//   A stages: [0, 36864)   (3 x 12288)
//   B stages: [36864, 49920) (3 x 4352)
// EPI: 1 gelu->fp16 (ldch), 2 +b1+b2+resid f32, 4 fp16 (ldch)
// ---------------------------------------------------------------------------
#define HG_A_ST  (256 * 24 * 2)               // 12288 B / stage
#define HG_B_ST  (16 * 136 * 2)               //  4352 B / stage
#define HG_B_OFS (3 * HG_A_ST)                // 36864
#define HG_SMEM  (3u * (HG_A_ST + HG_B_ST))   // 49920

template<int EPI>
__global__ __launch_bounds__(256, 1) void hgemm_kernel(
    const uint16_t* __restrict__ A, const uint16_t* __restrict__ Bm,
    float* __restrict__ C, uint16_t* __restrict__ Ch, int ldch,
    const float* __restrict__ bias1, const float* __restrict__ bias2,
    const float* __restrict__ resid,
    int M, int N, int K)
{
    extern __shared__ __align__(16) uint8_t hsm[];
    uint32_t sA = (uint32_t)__cvta_generic_to_shared(hsm);
    uint32_t sB = sA + HG_B_OFS;

    int tid = threadIdx.x;
    int bm = blockIdx.y, bn = blockIdx.x;
    int warp = tid >> 5, lane = tid & 31;
    int wm = (warp & 3) * 64;          // warp row base (4 m-warps)
    int wn = (warp >> 2) * 64;         // warp col base (2 n-warps)
    int g = lane >> 2, tg = lane & 3;

    int arow = tid >> 1, ak0 = (tid & 1) * 8;   // A: 2 uint4/thread/stage
    int bkr  = tid >> 4, bnc = (tid & 15) * 8;  // B: 1 uint4/thread/stage

    const uint16_t* pA = A  + (size_t)(bm * 256 + arow) * K + ak0;
    const uint16_t* pB = Bm + (size_t)bkr * N + bn * 128 + bnc;
    const size_t A2 = (size_t)128 * K;          // second A row block

    int sub = lane >> 3, r8 = lane & 7;
    int a_lane_off = (((sub & 1) * 8 + r8) * 24 + (sub >> 1) * 8) * 2;
    int b_lane_off = (((sub & 1) * 8 + r8) * 136 + (sub >> 1) * 8) * 2;

    uint32_t aDst = sA + arow * 48 + ak0 * 2;
    uint32_t bDst = sB + bkr * 272 + bnc * 2;

    float acc[4][8][4];
    #pragma unroll
    for (int i = 0; i < 4; i++)
        #pragma unroll
        for (int j = 0; j < 8; j++)
            #pragma unroll
            for (int r = 0; r < 4; r++) acc[i][j][r] = 0.0f;

    int NK = K >> 4;
    // prologue: stages 0, 1
    cpa16(aDst,                pA);
    cpa16(aDst + 128 * 48,     pA + A2);
    cpa16(bDst,                pB);
    CP_COMMIT();
    cpa16(aDst + HG_A_ST,            pA + 16);
    cpa16(aDst + HG_A_ST + 128 * 48, pA + A2 + 16);
    cpa16(bDst + HG_B_ST,            pB + (size_t)16 * N);
    CP_COMMIT();

    for (int it = 0; it < NK; it++) {
        asm volatile("cp.async.wait_group 1;" ::: "memory");
        __syncthreads();

        // prefetch stage it+2 (overlaps MMA below); commit keeps count exact
        if (it + 2 < NK) {
            int s2 = (it + 2) % 3;
            int k2 = (it + 2) * 16;
            cpa16(aDst + s2 * HG_A_ST,            pA + k2);
            cpa16(aDst + s2 * HG_A_ST + 128 * 48, pA + A2 + k2);
            cpa16(bDst + s2 * HG_B_ST,            pB + (size_t)k2 * N);
        }
        CP_COMMIT();

        int s = it % 3;
        uint32_t af[4][4];
        #pragma unroll
        for (int i = 0; i < 4; i++) {
            int m0 = wm + i * 16;
            ldsm4(af[i], sA + s * HG_A_ST + m0 * 48 + a_lane_off);
        }
        #pragma unroll
        for (int jj = 0; jj < 4; jj++) {
            int n0 = wn + jj * 16;
            uint32_t bf4[4];
            ldsm4t(bf4, sB + s * HG_B_ST + n0 * 2 + b_lane_off);
            #pragma unroll
            for (int hf = 0; hf < 2; hf++) {
                int j = jj * 2 + hf;
                #pragma unroll
                for (int i = 0; i < 4; i++)
                    mma16(acc[i][j], af[i], bf4 + hf * 2);
            }
        }
        __syncthreads();
    }

    #pragma unroll
    for (int i = 0; i < 4; i++) {
        #pragma unroll
        for (int j = 0; j < 8; j++) {
            int row0 = bm * 256 + wm + i * 16 + g;
            int col  = bn * 128 + wn + j * 8 + tg * 2;
            #pragma unroll
            for (int rr = 0; rr < 2; rr++) {
                int row = row0 + rr * 8;
                float v0 = acc[i][j][rr * 2 + 0];
                float v1 = acc[i][j][rr * 2 + 1];
                if (EPI == 1 || EPI == 4) {
                    if (EPI == 1) { v0 = gelu_tanh(v0); v1 = gelu_tanh(v1); }
                    ushort2 o;
                    o.x = f2h(v0); o.y = f2h(v1);
                    *(ushort2*)(Ch + (size_t)row * ldch + col) = o;
                } else {
                    size_t idx = (size_t)row * N + col;
                    v0 += bias1[col] + bias2[col] + resid[idx];
                    v1 += bias1[col + 1] + bias2[col + 1] + resid[idx + 1];
                    C[idx]     = v0;
                    C[idx + 1] = v1;
                }
            }
        }
    }
}

// ---------------------------------------------------------------------------
// fp16 flash attention. Grid (S/128, H, B), 256 thr = 8 warps, 16 q-rows per
// warp. Reads q/k/v from fused [M][QKV_LD]; writes av into fused hav buffer.
// K/V tiles (64 keys) double-buffered via cp.async; row stride 72 fp16.
// ---------------------------------------------------------------------------
#define AT_BUF   9216u           // one 64x72 fp16 buffer, bytes
#define AT_STAGE (2u * AT_BUF)   // K, V
#define AT_SMEM  (2u * AT_STAGE) // 36864 bytes

__global__ __launch_bounds__(256) void fattn_kernel(
    const uint16_t* __restrict__ qkv, uint16_t* __restrict__ hav)
{
    extern __shared__ __align__(16) uint16_t sm[];
    int h = blockIdx.y, b = blockIdx.z;
    int tid = threadIdx.x, warp = tid >> 5, lane = tid & 31;
    int g = lane >> 2, tg = lane & 3, r8 = lane & 7;
    uint32_t smb = (uint32_t)__cvta_generic_to_shared(sm);

    // ---- stage Q (aliases stage area), load ldmatrix fragments ----
    {
        int row = tid >> 1;
        int half = (tid & 1) * 32;
        size_t gq = ((size_t)b * S_ + blockIdx.x * 128 + row) * QKV_LD + h * HD_ + half;
        #pragma unroll
        for (int i = 0; i < 4; i++)
            *(uint4*)(sm + row * 72 + half + i * 8) = *(const uint4*)(qkv + gq + i * 8);
    }
    __syncthreads();
    uint32_t qf[4][4];
    {
        int qr = warp * 16 + r8 + ((lane >> 3) & 1) * 8;
        #pragma unroll
        for (int ks = 0; ks < 4; ks++) {
            int col = ks * 16 + ((lane >> 4) & 1) * 8;
            ldsm4(qf[ks], smb + (qr * 72 + col) * 2);
        }
    }
    __syncthreads();

    // cp.async loader: 2 threads per row; buf 0 = K (+D_), buf 1 = V (+2*D_)
    int buf = tid >> 7;
    int u   = (tid & 127) >> 1;
    int hc  = (tid & 1) * 64;
    const uint16_t* gsrc = qkv + ((size_t)b * S_ + u) * QKV_LD +
                           (buf + 1) * D_ + h * HD_ + (tid & 1) * 32;
    uint32_t sdst = smb + buf * AT_BUF + u * 144 + hc;

    float o[8][4];
    #pragma unroll
    for (int j = 0; j < 8; j++)
        #pragma unroll
        for (int r = 0; r < 4; r++) o[j][r] = 0.0f;
    float m0 = -1e30f, m1 = -1e30f, l0 = 0.0f, l1 = 0.0f;

    {
        #pragma unroll
        for (int i = 0; i < 4; i++) cpa16(sdst + i * 16, gsrc + i * 8);
        CP_COMMIT();
    }

    for (int it = 0; it < S_ / 64; it++) {
        if (it + 1 < S_ / 64) {
            const uint16_t* src = gsrc + (size_t)(it + 1) * 64 * QKV_LD;
            uint32_t dst = sdst + ((it + 1) & 1) * AT_STAGE;
            #pragma unroll
            for (int i = 0; i < 4; i++) cpa16(dst + i * 16, src + i * 8);
            CP_COMMIT();
            asm volatile("cp.async.wait_group 1;");
        } else {
            asm volatile("cp.async.wait_group 0;");
        }
        __syncthreads();

        uint32_t kb = smb + (it & 1) * AT_STAGE;
        uint32_t vb = kb + AT_BUF;

        float sc[8][4];
        #pragma unroll
        for (int j = 0; j < 8; j++)
            #pragma unroll
            for (int r = 0; r < 4; r++) sc[j][r] = 0.0f;

        #pragma unroll
        for (int ks = 0; ks < 4; ks++) {
            #pragma unroll
            for (int j2 = 0; j2 < 4; j2++) {
                int key = j2 * 16 + r8 + ((lane >> 4) & 1) * 8;
                int col = ks * 16 + ((lane >> 3) & 1) * 8;
                uint32_t bf4[4];
                ldsm4(bf4, kb + key * 144 + col * 2);
                mma16(sc[2*j2],   qf[ks], &bf4[0]);
                mma16(sc[2*j2+1], qf[ks], &bf4[2]);
            }
        }

        const float scale = 0.125f;
        float mx0 = -1e30f, mx1 = -1e30f;
        #pragma unroll
        for (int j = 0; j < 8; j++) {
            sc[j][0] *= scale; sc[j][1] *= scale;
            sc[j][2] *= scale; sc[j][3] *= scale;
            mx0 = fmaxf(mx0, fmaxf(sc[j][0], sc[j][1]));
            mx1 = fmaxf(mx1, fmaxf(sc[j][2], sc[j][3]));
        }
        mx0 = fmaxf(mx0, __shfl_xor_sync(0xffffffffu, mx0, 1));
        mx0 = fmaxf(mx0, __shfl_xor_sync(0xffffffffu, mx0, 2));
        mx1 = fmaxf(mx1, __shfl_xor_sync(0xffffffffu, mx1, 1));
        mx1 = fmaxf(mx1, __shfl_xor_sync(0xffffffffu, mx1, 2));
        float nm0 = fmaxf(m0, mx0), nm1 = fmaxf(m1, mx1);
        float c0 = __expf(m0 - nm0), c1 = __expf(m1 - nm1);
        m0 = nm0; m1 = nm1;
        l0 *= c0; l1 *= c1;
        #pragma unroll
        for (int j = 0; j < 8; j++) {
            o[j][0] *= c0; o[j][1] *= c0;
            o[j][2] *= c1; o[j][3] *= c1;
        }
        #pragma unroll
        for (int j = 0; j < 8; j++) {
            float p0 = __expf(sc[j][0] - m0); sc[j][0] = p0; l0 += p0;
            float p1 = __expf(sc[j][1] - m0); sc[j][1] = p1; l0 += p1;
            float p2 = __expf(sc[j][2] - m1); sc[j][2] = p2; l1 += p2;
            float p3 = __expf(sc[j][3] - m1); sc[j][3] = p3; l1 += p3;
        }

        #pragma unroll
        for (int kt = 0; kt < 4; kt++) {
            int ja = 2 * kt, jb = 2 * kt + 1;
            uint32_t pa[4];
            pa[0] = pack2h(sc[ja][0], sc[ja][1]);
            pa[1] = pack2h(sc[ja][2], sc[ja][3]);
            pa[2] = pack2h(sc[jb][0], sc[jb][1]);
            pa[3] = pack2h(sc[jb][2], sc[jb][3]);
            #pragma unroll
            for (int jn2 = 0; jn2 < 4; jn2++) {
                int key = kt * 16 + r8 + ((lane >> 3) & 1) * 8;
                int col = jn2 * 16 + ((lane >> 4) & 1) * 8;
                uint32_t vf4[4];
                ldsm4t(vf4, vb + key * 144 + col * 2);
                mma16(o[2*jn2],   pa, &vf4[0]);
                mma16(o[2*jn2+1], pa, &vf4[2]);
            }
        }
        __syncthreads();
    }

    l0 += __shfl_xor_sync(0xffffffffu, l0, 1);
    l0 += __shfl_xor_sync(0xffffffffu, l0, 2);
    l1 += __shfl_xor_sync(0xffffffffu, l1, 1);
    l1 += __shfl_xor_sync(0xffffffffu, l1, 2);
    float inv0 = 1.0f / l0, inv1 = 1.0f / l1;

    int row0 = blockIdx.x * 128 + warp * 16 + g;
    size_t base0 = ((size_t)b * S_ + row0) * HAV_LD + MLP_ + h * HD_;
    size_t base1 = base0 + (size_t)8 * HAV_LD;
    #pragma unroll
    for (int j = 0; j < 8; j++) {
        int col = j * 8 + tg * 2;
        ushort2 w0, w1;
        w0.x = f2h(o[j][0] * inv0); w0.y = f2h(o[j][1] * inv0);
        w1.x = f2h(o[j][2] * inv1); w1.y = f2h(o[j][3] * inv1);
        *(ushort2*)(hav + base0 + col) = w0;
        *(ushort2*)(hav + base1 + col) = w1;
    }
}

// ---------------------------------------------------------------------------
// Launch
// ---------------------------------------------------------------------------
extern "C" void kernel_launch(void* const* d_in, const int* in_sizes, int n_in,
                              void* d_out, int out_size)
{
    const float* x          = (const float*)d_in[0];
    const float* pns        = (const float*)d_in[1];
    const float* w_mlp_in   = (const float*)d_in[2];
    const float* wq         = (const float*)d_in[3];
    const float* wk         = (const float*)d_in[4];
    const float* wv         = (const float*)d_in[5];
    const float* w_mlp_out  = (const float*)d_in[6];
    const float* b_mlp_out  = (const float*)d_in[7];
    const float* w_attn_out = (const float*)d_in[8];
    const float* b_attn_out = (const float*)d_in[9];
    float* out = (float*)d_out;

    uint16_t *xn, *qkv, *hav, *w1, *wqkv, *w2;
    cudaGetSymbolAddress((void**)&xn,   g_xn);
    cudaGetSymbolAddress((void**)&qkv,  g_qkv);
    cudaGetSymbolAddress((void**)&hav,  g_hav);
    cudaGetSymbolAddress((void**)&w1,   g_w1);
    cudaGetSymbolAddress((void**)&wqkv, g_wqkv);
    cudaGetSymbolAddress((void**)&w2,   g_w2);

    cudaFuncSetAttribute(fattn_kernel, cudaFuncAttributeMaxDynamicSharedMemorySize, AT_SMEM);
    cudaFuncSetAttribute(hgemm_kernel<1>, cudaFuncAttributeMaxDynamicSharedMemorySize, HG_SMEM);
    cudaFuncSetAttribute(hgemm_kernel<2>, cudaFuncAttributeMaxDynamicSharedMemorySize, HG_SMEM);
    cudaFuncSetAttribute(hgemm_kernel<4>, cudaFuncAttributeMaxDynamicSharedMemorySize, HG_SMEM);

    // 0. weight converts
    const int DM = D_ * MLP_, DD = D_ * D_;
    cvt_kernel<<<DM / 1024, 256>>>(w_mlp_in, w1, DM);
    cvtq_kernel<<<DD / 1024, 256>>>(wq, wqkv, 0);
    cvtq_kernel<<<DD / 1024, 256>>>(wk, wqkv, D_);
    cvtq_kernel<<<DD / 1024, 256>>>(wv, wqkv, 2 * D_);
    cvt_kernel<<<DM / 1024, 256>>>(w_mlp_out,  w2, DM);                 // rows 0..4095
    cvt_kernel<<<DD / 1024, 256>>>(w_attn_out, w2 + (size_t)MLP_ * D_, DD); // rows 4096..5119

    // 1. RMSNorm -> xn fp16
    rmsnorm_kernel<<<MROWS, 256>>>(x, pns, xn);

    // 2. h = gelu(xn @ w_mlp_in) -> hav cols [0, 4096)
    dim3 g_mlp(MLP_ / 128, MROWS / 256);
    hgemm_kernel<1><<<g_mlp, 256, HG_SMEM>>>(xn, w1, nullptr, hav, HAV_LD,
                                             nullptr, nullptr, nullptr,
                                             MROWS, MLP_, D_);

    // 3. qkv = xn @ [wq|wk|wv]  (one fused GEMM, N = 3072)
    dim3 g_qkv(QKV_LD / 128, MROWS / 256);
    hgemm_kernel<4><<<g_qkv, 256, HG_SMEM>>>(xn, wqkv, nullptr, qkv, QKV_LD,
                                             nullptr, nullptr, nullptr,
                                             MROWS, QKV_LD, D_);

    // 4. flash attention -> hav cols [4096, 5120)
    dim3 g_attn(S_ / 128, H_, B_);
    fattn_kernel<<<g_attn, 256, AT_SMEM>>>(qkv, hav);

    // 5. out = resid + [h|av] @ [w_mlp_out; w_attn_out] + b_mlp + b_attn
    dim3 g_out(D_ / 128, MROWS / 256);
    hgemm_kernel<2><<<g_out, 256, HG_SMEM>>>(hav, w2, out, nullptr, 0,
                                             b_mlp_out, b_attn_out, x,
                                             MROWS, D_, HAV_LD);
}